// round 10
// baseline (speedup 1.0000x reference)
#include <cuda_runtime.h>
#include <cuda_bf16.h>
#include <cstdint>

#define N_TOK 8192
#define DIM   64
#define BM    64
#define BN    128
#define HALF_KV 4096
#define NITER (HALF_KV / BN)   // 32

// ---------------- global scratch ----------------
__device__ __nv_bfloat16 g_Qh[N_TOK * DIM], g_Ql[N_TOK * DIM];
__device__ __nv_bfloat16 g_Kh[N_TOK * DIM], g_Kl[N_TOK * DIM];
__device__ __nv_bfloat16 g_Xth[DIM * N_TOK], g_Xtl[DIM * N_TOK];
__device__ float g_Opart[2][N_TOK * DIM];
__device__ float g_mpart[2][N_TOK];
__device__ float g_lpart[2][N_TOK];

// ---------------- helpers ----------------
__device__ __forceinline__ uint32_t smem_u32(const void* p) {
    uint32_t a;
    asm("{ .reg .u64 t; cvta.to.shared.u64 t, %1; cvt.u32.u64 %0, t; }" : "=r"(a) : "l"(p));
    return a;
}
__device__ __forceinline__ uint32_t swz8(uint32_t row, uint32_t ch) {
    return row * 128u + ((ch ^ (row & 7u)) << 4);
}
__device__ __forceinline__ uint32_t swz16(uint32_t row, uint32_t ch) {
    return row * 256u + ((ch ^ (row & 7u)) << 4);
}
__device__ __forceinline__ void ldsm4(uint32_t& r0, uint32_t& r1, uint32_t& r2,
                                      uint32_t& r3, uint32_t addr) {
    asm volatile("ldmatrix.sync.aligned.m8n8.x4.shared.b16 {%0,%1,%2,%3}, [%4];"
                 : "=r"(r0), "=r"(r1), "=r"(r2), "=r"(r3) : "r"(addr));
}
__device__ __forceinline__ void mma16816(float* c, const uint32_t* a, uint32_t b0,
                                         uint32_t b1) {
    asm volatile(
        "mma.sync.aligned.m16n8k16.row.col.f32.bf16.bf16.f32 "
        "{%0,%1,%2,%3}, {%4,%5,%6,%7}, {%8,%9}, {%0,%1,%2,%3};"
        : "+f"(c[0]), "+f"(c[1]), "+f"(c[2]), "+f"(c[3])
        : "r"(a[0]), "r"(a[1]), "r"(a[2]), "r"(a[3]), "r"(b0), "r"(b1));
}
__device__ __forceinline__ uint32_t cvt2bf(float lo, float hi) {
    uint32_t r;
    asm("cvt.rn.bf16x2.f32 %0, %1, %2;" : "=r"(r) : "f"(hi), "f"(lo));
    return r;
}
__device__ __forceinline__ void split2f(float a, float b, uint32_t& hi, uint32_t& lo) {
    hi = cvt2bf(a, b);
    float fa = __uint_as_float(hi << 16);
    float fb = __uint_as_float(hi & 0xFFFF0000u);
    lo = cvt2bf(a - fa, b - fb);
}
__device__ __forceinline__ void cpa16(uint32_t dst, const void* src) {
    asm volatile("cp.async.cg.shared.global [%0], [%1], 16;" :: "r"(dst), "l"(src));
}
#define CP_COMMIT() asm volatile("cp.async.commit_group;" ::: "memory")
#define CP_WAIT(n)  asm volatile("cp.async.wait_group %0;" :: "n"(n) : "memory")

// ---- packed f32x2 (for proj) ----
__device__ __forceinline__ unsigned long long pk2(float a, float b) {
    unsigned long long r;
    asm("mov.b64 %0, {%1, %2};" : "=l"(r) : "f"(a), "f"(b));
    return r;
}
__device__ __forceinline__ void upk2(unsigned long long v, float& a, float& b) {
    asm("mov.b64 {%0, %1}, %2;" : "=f"(a), "=f"(b) : "l"(v));
}
__device__ __forceinline__ unsigned long long fma2(unsigned long long a,
                                                   unsigned long long b,
                                                   unsigned long long c) {
    unsigned long long d;
    asm("fma.rn.f32x2 %0, %1, %2, %3;" : "=l"(d) : "l"(a), "l"(b), "l"(c));
    return d;
}

// ---------------- projection + split kernel (f32x2 row-pair packed) ----------------
__global__ __launch_bounds__(256) void proj_kernel(const float* __restrict__ x,
                                                   const float* __restrict__ R,
                                                   const float* __restrict__ E) {
    extern __shared__ float psm[];
    float* Rs = psm;                 // 4096
    float* Es = psm + 4096;          // 4096
    float* xs = psm + 8192;          // 32*65 padded
    int tid = threadIdx.x;
    int row0 = blockIdx.x * 32;
    {
        const float4* Rsrc = (const float4*)R;
        const float4* Esrc = (const float4*)E;
        float4* Rd = (float4*)Rs;
        float4* Ed = (float4*)Es;
#pragma unroll
        for (int i = tid; i < 1024; i += 256) { Rd[i] = Rsrc[i]; Ed[i] = Esrc[i]; }
    }
#pragma unroll
    for (int i = tid; i < 2048; i += 256) {
        int row = i >> 6, c = i & 63;
        xs[row * 65 + c] = x[(size_t)(row0 + row) * 64 + c];
    }
    __syncthreads();

#pragma unroll
    for (int i = tid; i < 2048; i += 256) {
        int d = i >> 5, row = i & 31;
        float xv = xs[row * 65 + d];
        __nv_bfloat16 xh = __float2bfloat16(xv);
        g_Xth[(size_t)d * N_TOK + row0 + row] = xh;
        g_Xtl[(size_t)d * N_TOK + row0 + row] =
            __float2bfloat16(xv - __bfloat162float(xh));
    }

    int ty = tid >> 6, col = tid & 63;
    unsigned long long aq2[4], ak2[4];
#pragma unroll
    for (int j = 0; j < 4; j++) { aq2[j] = 0ull; ak2[j] = 0ull; }
#pragma unroll 8
    for (int k = 0; k < 64; k++) {
        float rv = Rs[k * 64 + col];
        float ev = Es[k * 64 + col];
        unsigned long long rv2 = pk2(rv, rv);
        unsigned long long ev2 = pk2(ev, ev);
#pragma unroll
        for (int j = 0; j < 4; j++) {
            unsigned long long xp = pk2(xs[(8 * j + ty) * 65 + k],
                                        xs[(8 * j + 4 + ty) * 65 + k]);
            aq2[j] = fma2(xp, rv2, aq2[j]);
            ak2[j] = fma2(xp, ev2, ak2[j]);
        }
    }
#pragma unroll
    for (int j = 0; j < 4; j++) {
        float q0, q1, k0, k1;
        upk2(aq2[j], q0, q1);
        upk2(ak2[j], k0, k1);
        int rA = row0 + 8 * j + ty;
        int rB = rA + 4;
        q0 *= 0.125f; q1 *= 0.125f;
        __nv_bfloat16 qh0 = __float2bfloat16(q0);
        g_Qh[(size_t)rA * 64 + col] = qh0;
        g_Ql[(size_t)rA * 64 + col] = __float2bfloat16(q0 - __bfloat162float(qh0));
        __nv_bfloat16 qh1 = __float2bfloat16(q1);
        g_Qh[(size_t)rB * 64 + col] = qh1;
        g_Ql[(size_t)rB * 64 + col] = __float2bfloat16(q1 - __bfloat162float(qh1));
        __nv_bfloat16 kh0 = __float2bfloat16(k0);
        g_Kh[(size_t)rA * 64 + col] = kh0;
        g_Kl[(size_t)rA * 64 + col] = __float2bfloat16(k0 - __bfloat162float(kh0));
        __nv_bfloat16 kh1 = __float2bfloat16(k1);
        g_Kh[(size_t)rB * 64 + col] = kh1;
        g_Kl[(size_t)rB * 64 + col] = __float2bfloat16(k1 - __bfloat162float(kh1));
    }
}
#define PROJ_SMEM ((4096 + 4096 + 32 * 65) * 4)

// ---------------- fused flash attention (HMMA, 3 CTA/SM, single-buffered) ----------------
#define OFF_KH 0
#define OFF_KL 16384
#define OFF_XH 32768
#define OFF_XL 49152
#define SMEM_TOTAL 65536

__global__ __launch_bounds__(128, 3) void attn_kernel() {
    extern __shared__ char sm[];
    uint32_t sb = smem_u32(sm);
    const int tid = threadIdx.x;
    const int lane = tid & 31;
    const int w = tid >> 5;
    const int m0 = w * 16;
    const int rb = blockIdx.x >> 1;
    const int half = blockIdx.x & 1;
    const int row0 = rb * BM;
    const int jb0 = half * HALF_KV;
    const int g = lane >> 3, rr = lane & 7;

    // ---- stage Q (hi/lo) into X smem region, build A-fragments once ----
#pragma unroll
    for (int i = tid; i < 64 * 8; i += 128) {
        int row = i >> 3, ch = i & 7;
        uint32_t sw = swz8(row, ch);
        *(uint4*)(sm + OFF_XH + sw) = *(const uint4*)(g_Qh + (size_t)(row0 + row) * DIM + ch * 8);
        *(uint4*)(sm + OFF_XL + sw) = *(const uint4*)(g_Ql + (size_t)(row0 + row) * DIM + ch * 8);
    }
    __syncthreads();

    uint32_t qh[4][4], ql[4][4];
    {
        int arow = m0 + ((g & 1) << 3) + rr;
#pragma unroll
        for (int ks = 0; ks < 4; ks++) {
            uint32_t off = swz8(arow, ks * 2 + (g >> 1));
            ldsm4(qh[ks][0], qh[ks][1], qh[ks][2], qh[ks][3], sb + OFF_XH + off);
            ldsm4(ql[ks][0], ql[ks][1], ql[ks][2], ql[ks][3], sb + OFF_XL + off);
        }
    }
    __syncthreads();   // Q frags built; X region reusable

    float o[8][4];
#pragma unroll
    for (int t = 0; t < 8; t++)
#pragma unroll
        for (int j = 0; j < 4; j++) o[t][j] = 0.f;
    float mc0 = -3.0e38f, mc1 = -3.0e38f, lc0 = 0.f, lc1 = 0.f;

    for (int it = 0; it < NITER; it++) {
        int jb = jb0 + it * BN;

        // ---- issue K(it) (group), then X(it) (group) ----
#pragma unroll
        for (int i = tid; i < 128 * 8; i += 128) {
            int row = i >> 3, ch = i & 7;
            uint32_t sw = swz8(row, ch);
            cpa16(sb + OFF_KH + sw, g_Kh + (size_t)(jb + row) * DIM + ch * 8);
            cpa16(sb + OFF_KL + sw, g_Kl + (size_t)(jb + row) * DIM + ch * 8);
        }
        CP_COMMIT();
#pragma unroll
        for (int i = tid; i < 64 * 16; i += 128) {
            int row = i >> 4, ch = i & 15;
            uint32_t sw = swz16(row, ch);
            cpa16(sb + OFF_XH + sw, g_Xth + (size_t)row * N_TOK + jb + ch * 8);
            cpa16(sb + OFF_XL + sw, g_Xtl + (size_t)row * N_TOK + jb + ch * 8);
        }
        CP_COMMIT();
        CP_WAIT(1);        // K(it) done; X(it) streams under GEMM1
        __syncthreads();

        // ---- GEMM1: S = Qh*Kh + Qh*Kl + Ql*Kh ----
        float s[16][4];
#pragma unroll
        for (int t = 0; t < 16; t++)
#pragma unroll
            for (int j = 0; j < 4; j++) s[t][j] = 0.f;
#pragma unroll
        for (int np = 0; np < 8; np++) {
            int brow = np * 16 + ((g >> 1) << 3) + rr;
#pragma unroll
            for (int ks = 0; ks < 4; ks++) {
                uint32_t off = swz8(brow, ks * 2 + (g & 1));
                uint32_t b0, b1, b2, b3, c0, c1, c2, c3;
                ldsm4(b0, b1, b2, b3, sb + OFF_KH + off);
                ldsm4(c0, c1, c2, c3, sb + OFF_KL + off);
                mma16816(s[2 * np],     qh[ks], b0, b1);
                mma16816(s[2 * np + 1], qh[ks], b2, b3);
                mma16816(s[2 * np],     qh[ks], c0, c1);
                mma16816(s[2 * np + 1], qh[ks], c2, c3);
                mma16816(s[2 * np],     ql[ks], b0, b1);
                mma16816(s[2 * np + 1], ql[ks], b2, b3);
            }
        }

        CP_WAIT(0);        // X(it) landed
        __syncthreads();   // X stores visible CTA-wide

        // ---- row max ----
        float mx0 = -3.0e38f, mx1 = -3.0e38f;
#pragma unroll
        for (int t = 0; t < 16; t++) {
            mx0 = fmaxf(mx0, fmaxf(s[t][0], s[t][1]));
            mx1 = fmaxf(mx1, fmaxf(s[t][2], s[t][3]));
        }
        mx0 = fmaxf(mx0, __shfl_xor_sync(0xffffffffu, mx0, 1));
        mx0 = fmaxf(mx0, __shfl_xor_sync(0xffffffffu, mx0, 2));
        mx1 = fmaxf(mx1, __shfl_xor_sync(0xffffffffu, mx1, 1));
        mx1 = fmaxf(mx1, __shfl_xor_sync(0xffffffffu, mx1, 2));
        float mn0 = fmaxf(mc0, mx0), mn1 = fmaxf(mc1, mx1);
        float sc0 = __expf(mc0 - mn0), sc1 = __expf(mc1 - mn1);
        mc0 = mn0; mc1 = mn1;

        // ---- rescale O ----
#pragma unroll
        for (int t = 0; t < 8; t++) {
            o[t][0] *= sc0; o[t][1] *= sc0;
            o[t][2] *= sc1; o[t][3] *= sc1;
        }

        // ---- interleaved: exp/split chunk kt, then its GEMM2 MMAs ----
        float rs0 = 0.f, rs1 = 0.f;
#pragma unroll
        for (int kt = 0; kt < 8; kt++) {
            float p0 = __expf(s[2 * kt][0] - mn0);
            float p1 = __expf(s[2 * kt][1] - mn0);
            float p2 = __expf(s[2 * kt][2] - mn1);
            float p3 = __expf(s[2 * kt][3] - mn1);
            float p4 = __expf(s[2 * kt + 1][0] - mn0);
            float p5 = __expf(s[2 * kt + 1][1] - mn0);
            float p6 = __expf(s[2 * kt + 1][2] - mn1);
            float p7 = __expf(s[2 * kt + 1][3] - mn1);
            rs0 += (p0 + p1) + (p4 + p5);
            rs1 += (p2 + p3) + (p6 + p7);
            uint32_t pa[4], pb[4];
            split2f(p0, p1, pa[0], pb[0]);
            split2f(p2, p3, pa[1], pb[1]);
            split2f(p4, p5, pa[2], pb[2]);
            split2f(p6, p7, pa[3], pb[3]);
#pragma unroll
            for (int np = 0; np < 4; np++) {
                int brow = np * 16 + ((g >> 1) << 3) + rr;
                uint32_t off = swz16(brow, kt * 2 + (g & 1));
                uint32_t x0, x1, x2, x3, y0, y1, y2, y3;
                ldsm4(x0, x1, x2, x3, sb + OFF_XH + off);
                ldsm4(y0, y1, y2, y3, sb + OFF_XL + off);
                mma16816(o[2 * np],     pa, x0, x1);
                mma16816(o[2 * np + 1], pa, x2, x3);
                mma16816(o[2 * np],     pa, y0, y1);
                mma16816(o[2 * np + 1], pa, y2, y3);
                mma16816(o[2 * np],     pb, x0, x1);
                mma16816(o[2 * np + 1], pb, x2, x3);
            }
        }
        rs0 += __shfl_xor_sync(0xffffffffu, rs0, 1);
        rs0 += __shfl_xor_sync(0xffffffffu, rs0, 2);
        rs1 += __shfl_xor_sync(0xffffffffu, rs1, 1);
        rs1 += __shfl_xor_sync(0xffffffffu, rs1, 2);
        lc0 = lc0 * sc0 + rs0;
        lc1 = lc1 * sc1 + rs1;

        __syncthreads();   // K/X buffers consumed; safe to refill next iter
    }

    // ---- epilogue ----
    {
        int q = lane >> 2;
        int cb = (lane & 3) * 2;
        int r_lo = row0 + m0 + q;
        int r_hi = r_lo + 8;
        float* olo = g_Opart[half] + (size_t)r_lo * DIM;
        float* ohi = g_Opart[half] + (size_t)r_hi * DIM;
#pragma unroll
        for (int t = 0; t < 8; t++) {
            olo[t * 8 + cb]     = o[t][0];
            olo[t * 8 + cb + 1] = o[t][1];
            ohi[t * 8 + cb]     = o[t][2];
            ohi[t * 8 + cb + 1] = o[t][3];
        }
        if ((lane & 3) == 0) {
            g_mpart[half][r_lo] = mc0; g_mpart[half][r_hi] = mc1;
            g_lpart[half][r_lo] = lc0; g_lpart[half][r_hi] = lc1;
        }
    }
}

// ---------------- combine ----------------
__global__ __launch_bounds__(256) void combine_kernel(float* __restrict__ out) {
    int idx = blockIdx.x * 256 + threadIdx.x;
    int row = idx >> 6;
    int c = idx & 63;
    float m0 = g_mpart[0][row], m1 = g_mpart[1][row];
    float M = fmaxf(m0, m1);
    float w0 = __expf(m0 - M), w1 = __expf(m1 - M);
    float inv = 1.0f / (g_lpart[0][row] * w0 + g_lpart[1][row] * w1);
    out[(size_t)row * DIM + c] =
        (g_Opart[0][(size_t)row * DIM + c] * w0 + g_Opart[1][(size_t)row * DIM + c] * w1) * inv;
}

extern "C" void kernel_launch(void* const* d_in, const int* in_sizes, int n_in,
                              void* d_out, int out_size) {
    const float* x = (const float*)d_in[0];
    const float* R = (const float*)d_in[1];
    const float* E = (const float*)d_in[2];
    float* out = (float*)d_out;

    cudaFuncSetAttribute(proj_kernel, cudaFuncAttributeMaxDynamicSharedMemorySize, PROJ_SMEM);
    proj_kernel<<<N_TOK / 32, 256, PROJ_SMEM>>>(x, R, E);

    cudaFuncSetAttribute(attn_kernel, cudaFuncAttributeMaxDynamicSharedMemorySize, SMEM_TOTAL);
    attn_kernel<<<(N_TOK / BM) * 2, 128, SMEM_TOTAL>>>();

    combine_kernel<<<(N_TOK * DIM) / 256, 256>>>(out);
}

// round 11
// speedup vs baseline: 1.4792x; 1.4792x over previous
#include <cuda_runtime.h>
#include <cuda_bf16.h>
#include <cuda_fp16.h>
#include <cstdint>

#define N_TOK 8192
#define DIM   64
#define BM    64
#define BN    128
#define HALF_KV 4096
#define NITER (HALF_KV / BN)   // 32

// ---------------- global scratch ----------------
__device__ __nv_bfloat16 g_Qh[N_TOK * DIM], g_Ql[N_TOK * DIM];
__device__ __nv_bfloat16 g_Kh[N_TOK * DIM], g_Kl[N_TOK * DIM];
__device__ __half g_Xt[DIM * N_TOK];
__device__ float g_Opart[2][N_TOK * DIM];
__device__ float g_mpart[2][N_TOK];
__device__ float g_lpart[2][N_TOK];

// ---------------- helpers ----------------
__device__ __forceinline__ uint32_t smem_u32(const void* p) {
    uint32_t a;
    asm("{ .reg .u64 t; cvta.to.shared.u64 t, %1; cvt.u32.u64 %0, t; }" : "=r"(a) : "l"(p));
    return a;
}
__device__ __forceinline__ uint32_t swz8(uint32_t row, uint32_t ch) {
    return row * 128u + ((ch ^ (row & 7u)) << 4);
}
__device__ __forceinline__ uint32_t swz16(uint32_t row, uint32_t ch) {
    return row * 256u + ((ch ^ (row & 7u)) << 4);
}
__device__ __forceinline__ void ldsm4(uint32_t& r0, uint32_t& r1, uint32_t& r2,
                                      uint32_t& r3, uint32_t addr) {
    asm volatile("ldmatrix.sync.aligned.m8n8.x4.shared.b16 {%0,%1,%2,%3}, [%4];"
                 : "=r"(r0), "=r"(r1), "=r"(r2), "=r"(r3) : "r"(addr));
}
__device__ __forceinline__ void mma16816(float* c, const uint32_t* a, uint32_t b0,
                                         uint32_t b1) {
    asm volatile(
        "mma.sync.aligned.m16n8k16.row.col.f32.bf16.bf16.f32 "
        "{%0,%1,%2,%3}, {%4,%5,%6,%7}, {%8,%9}, {%0,%1,%2,%3};"
        : "+f"(c[0]), "+f"(c[1]), "+f"(c[2]), "+f"(c[3])
        : "r"(a[0]), "r"(a[1]), "r"(a[2]), "r"(a[3]), "r"(b0), "r"(b1));
}
__device__ __forceinline__ void mma16816h(float* c, const uint32_t* a, uint32_t b0,
                                          uint32_t b1) {
    asm volatile(
        "mma.sync.aligned.m16n8k16.row.col.f32.f16.f16.f32 "
        "{%0,%1,%2,%3}, {%4,%5,%6,%7}, {%8,%9}, {%0,%1,%2,%3};"
        : "+f"(c[0]), "+f"(c[1]), "+f"(c[2]), "+f"(c[3])
        : "r"(a[0]), "r"(a[1]), "r"(a[2]), "r"(a[3]), "r"(b0), "r"(b1));
}
// packed f16x2 convert: low16 = h(lo), high16 = h(hi)
__device__ __forceinline__ uint32_t cvt2h(float lo, float hi) {
    uint32_t r;
    asm("cvt.rn.f16x2.f32 %0, %1, %2;" : "=r"(r) : "f"(hi), "f"(lo));
    return r;
}
__device__ __forceinline__ void cpa16(uint32_t dst, const void* src) {
    asm volatile("cp.async.cg.shared.global [%0], [%1], 16;" :: "r"(dst), "l"(src));
}
#define CP_COMMIT() asm volatile("cp.async.commit_group;" ::: "memory")
#define CP_WAIT(n)  asm volatile("cp.async.wait_group %0;" :: "n"(n) : "memory")

// ---------------- projection + split kernel ----------------
__global__ __launch_bounds__(256) void proj_kernel(const float* __restrict__ x,
                                                   const float* __restrict__ R,
                                                   const float* __restrict__ E) {
    extern __shared__ float psm[];
    float* Rs = psm;                 // 4096
    float* Es = psm + 4096;          // 4096
    float* xs = psm + 8192;          // 32*65 padded
    int tid = threadIdx.x;
    int row0 = blockIdx.x * 32;
    {
        const float4* Rsrc = (const float4*)R;
        const float4* Esrc = (const float4*)E;
        float4* Rd = (float4*)Rs;
        float4* Ed = (float4*)Es;
#pragma unroll
        for (int i = tid; i < 1024; i += 256) { Rd[i] = Rsrc[i]; Ed[i] = Esrc[i]; }
    }
#pragma unroll
    for (int i = tid; i < 2048; i += 256) {
        int row = i >> 6, c = i & 63;
        xs[row * 65 + c] = x[(size_t)(row0 + row) * 64 + c];
    }
    __syncthreads();

    // coalesced transposed fp16 store of x
#pragma unroll
    for (int i = tid; i < 2048; i += 256) {
        int d = i >> 5, row = i & 31;
        g_Xt[(size_t)d * N_TOK + row0 + row] = __float2half_rn(xs[row * 65 + d]);
    }

    int ty = tid >> 6, col = tid & 63;
    float aq[8], ak[8];
#pragma unroll
    for (int r = 0; r < 8; r++) { aq[r] = 0.f; ak[r] = 0.f; }
#pragma unroll 8
    for (int k = 0; k < 64; k++) {
        float rv = Rs[k * 64 + col];
        float ev = Es[k * 64 + col];
#pragma unroll
        for (int r = 0; r < 8; r++) {
            float xv = xs[(r * 4 + ty) * 65 + k];
            aq[r] = fmaf(xv, rv, aq[r]);
            ak[r] = fmaf(xv, ev, ak[r]);
        }
    }
#pragma unroll
    for (int r = 0; r < 8; r++) {
        int row = row0 + r * 4 + ty;
        float q = aq[r] * 0.125f;
        __nv_bfloat16 qh = __float2bfloat16(q);
        g_Qh[(size_t)row * 64 + col] = qh;
        g_Ql[(size_t)row * 64 + col] = __float2bfloat16(q - __bfloat162float(qh));
        __nv_bfloat16 kh = __float2bfloat16(ak[r]);
        g_Kh[(size_t)row * 64 + col] = kh;
        g_Kl[(size_t)row * 64 + col] = __float2bfloat16(ak[r] - __bfloat162float(kh));
    }
}
#define PROJ_SMEM ((4096 + 4096 + 32 * 65) * 4)

// ---------------- fused flash attention (HMMA, K dbl-buffered, fp16 GEMM2) ----------------
#define OFF_KH0 0
#define OFF_KL0 16384
#define OFF_KH1 32768
#define OFF_KL1 49152
#define OFF_X   65536
#define SMEM_TOTAL 81920

__global__ __launch_bounds__(128, 2) void attn_kernel() {
    extern __shared__ char sm[];
    uint32_t sb = smem_u32(sm);
    const int tid = threadIdx.x;
    const int lane = tid & 31;
    const int w = tid >> 5;
    const int m0 = w * 16;
    const int rb = blockIdx.x >> 1;
    const int half = blockIdx.x & 1;
    const int row0 = rb * BM;
    const int jb0 = half * HALF_KV;
    const int g = lane >> 3, rr = lane & 7;

    // ---- stage Q (hi/lo) into X smem region (8KB each), build A-fragments once ----
#pragma unroll
    for (int i = tid; i < 64 * 8; i += 128) {
        int row = i >> 3, ch = i & 7;
        uint32_t sw = swz8(row, ch);
        *(uint4*)(sm + OFF_X + sw) = *(const uint4*)(g_Qh + (size_t)(row0 + row) * DIM + ch * 8);
        *(uint4*)(sm + OFF_X + 8192 + sw) = *(const uint4*)(g_Ql + (size_t)(row0 + row) * DIM + ch * 8);
    }
    __syncthreads();

    uint32_t qh[4][4], ql[4][4];
    {
        int arow = m0 + ((g & 1) << 3) + rr;
#pragma unroll
        for (int ks = 0; ks < 4; ks++) {
            uint32_t off = swz8(arow, ks * 2 + (g >> 1));
            ldsm4(qh[ks][0], qh[ks][1], qh[ks][2], qh[ks][3], sb + OFF_X + off);
            ldsm4(ql[ks][0], ql[ks][1], ql[ks][2], ql[ks][3], sb + OFF_X + 8192 + off);
        }
    }
    __syncthreads();   // Q frags built; X region reusable

    // ---- prologue: issue K(0) into buffer 0 ----
#pragma unroll
    for (int i = tid; i < 128 * 8; i += 128) {
        int row = i >> 3, ch = i & 7;
        uint32_t sw = swz8(row, ch);
        cpa16(sb + OFF_KH0 + sw, g_Kh + (size_t)(jb0 + row) * DIM + ch * 8);
        cpa16(sb + OFF_KL0 + sw, g_Kl + (size_t)(jb0 + row) * DIM + ch * 8);
    }
    CP_COMMIT();

    float o[8][4];
#pragma unroll
    for (int t = 0; t < 8; t++)
#pragma unroll
        for (int j = 0; j < 4; j++) o[t][j] = 0.f;
    float mc0 = -3.0e38f, mc1 = -3.0e38f, lc0 = 0.f, lc1 = 0.f;

    for (int it = 0; it < NITER; it++) {
        int jb = jb0 + it * BN;
        __syncthreads();   // X buffer + K[(it+1)&1] free

        // ---- issue X(it): 64 d-rows x 128 tokens fp16, swizzled 256B rows ----
#pragma unroll
        for (int i = tid; i < 64 * 16; i += 128) {
            int row = i >> 4, ch = i & 15;
            uint32_t sw = swz16(row, ch);
            cpa16(sb + OFF_X + sw, g_Xt + (size_t)row * N_TOK + jb + ch * 8);
        }
        CP_COMMIT();
        // ---- issue K(it+1) ----
        if (it + 1 < NITER) {
            uint32_t kb_h = ((it + 1) & 1) ? OFF_KH1 : OFF_KH0;
            uint32_t kb_l = ((it + 1) & 1) ? OFF_KL1 : OFF_KL0;
            int jn = jb + BN;
#pragma unroll
            for (int i = tid; i < 128 * 8; i += 128) {
                int row = i >> 3, ch = i & 7;
                uint32_t sw = swz8(row, ch);
                cpa16(sb + kb_h + sw, g_Kh + (size_t)(jn + row) * DIM + ch * 8);
                cpa16(sb + kb_l + sw, g_Kl + (size_t)(jn + row) * DIM + ch * 8);
            }
            CP_COMMIT();
            CP_WAIT(2);    // K(it) done
        } else {
            CP_WAIT(1);    // K(it) done
        }
        __syncthreads();   // K(it) visible

        uint32_t kh_b = (it & 1) ? OFF_KH1 : OFF_KH0;
        uint32_t kl_b = (it & 1) ? OFF_KL1 : OFF_KL0;

        // ---- GEMM1: S = Qh*Kh + Qh*Kl + Ql*Kh (bf16 3-pass) ----
        float s[16][4];
#pragma unroll
        for (int t = 0; t < 16; t++)
#pragma unroll
            for (int j = 0; j < 4; j++) s[t][j] = 0.f;
#pragma unroll
        for (int np = 0; np < 8; np++) {
            int brow = np * 16 + ((g >> 1) << 3) + rr;
#pragma unroll
            for (int ks = 0; ks < 4; ks++) {
                uint32_t off = swz8(brow, ks * 2 + (g & 1));
                uint32_t b0, b1, b2, b3, c0, c1, c2, c3;
                ldsm4(b0, b1, b2, b3, sb + kh_b + off);
                ldsm4(c0, c1, c2, c3, sb + kl_b + off);
                mma16816(s[2 * np],     qh[ks], b0, b1);
                mma16816(s[2 * np + 1], qh[ks], b2, b3);
                mma16816(s[2 * np],     qh[ks], c0, c1);
                mma16816(s[2 * np + 1], qh[ks], c2, c3);
                mma16816(s[2 * np],     ql[ks], b0, b1);
                mma16816(s[2 * np + 1], ql[ks], b2, b3);
            }
        }

        // ---- X(it) visible before the interleaved region ----
        if (it + 1 < NITER) { CP_WAIT(1); } else { CP_WAIT(0); }
        __syncthreads();

        // ---- row max ----
        float mx0 = -3.0e38f, mx1 = -3.0e38f;
#pragma unroll
        for (int t = 0; t < 16; t++) {
            mx0 = fmaxf(mx0, fmaxf(s[t][0], s[t][1]));
            mx1 = fmaxf(mx1, fmaxf(s[t][2], s[t][3]));
        }
        mx0 = fmaxf(mx0, __shfl_xor_sync(0xffffffffu, mx0, 1));
        mx0 = fmaxf(mx0, __shfl_xor_sync(0xffffffffu, mx0, 2));
        mx1 = fmaxf(mx1, __shfl_xor_sync(0xffffffffu, mx1, 1));
        mx1 = fmaxf(mx1, __shfl_xor_sync(0xffffffffu, mx1, 2));
        float mn0 = fmaxf(mc0, mx0), mn1 = fmaxf(mc1, mx1);
        float sc0 = __expf(mc0 - mn0), sc1 = __expf(mc1 - mn1);
        mc0 = mn0; mc1 = mn1;

        // ---- rescale O ----
#pragma unroll
        for (int t = 0; t < 8; t++) {
            o[t][0] *= sc0; o[t][1] *= sc0;
            o[t][2] *= sc1; o[t][3] *= sc1;
        }

        // ---- interleaved: exp/cvt chunk kt, then its fp16 GEMM2 MMAs ----
        float rs0 = 0.f, rs1 = 0.f;
#pragma unroll
        for (int kt = 0; kt < 8; kt++) {
            float p0 = __expf(s[2 * kt][0] - mn0);
            float p1 = __expf(s[2 * kt][1] - mn0);
            float p2 = __expf(s[2 * kt][2] - mn1);
            float p3 = __expf(s[2 * kt][3] - mn1);
            float p4 = __expf(s[2 * kt + 1][0] - mn0);
            float p5 = __expf(s[2 * kt + 1][1] - mn0);
            float p6 = __expf(s[2 * kt + 1][2] - mn1);
            float p7 = __expf(s[2 * kt + 1][3] - mn1);
            rs0 += (p0 + p1) + (p4 + p5);
            rs1 += (p2 + p3) + (p6 + p7);
            uint32_t pa[4];
            pa[0] = cvt2h(p0, p1);
            pa[1] = cvt2h(p2, p3);
            pa[2] = cvt2h(p4, p5);
            pa[3] = cvt2h(p6, p7);
#pragma unroll
            for (int np = 0; np < 4; np++) {
                int brow = np * 16 + ((g >> 1) << 3) + rr;
                uint32_t off = swz16(brow, kt * 2 + (g & 1));
                uint32_t x0, x1, x2, x3;
                ldsm4(x0, x1, x2, x3, sb + OFF_X + off);
                mma16816h(o[2 * np],     pa, x0, x1);
                mma16816h(o[2 * np + 1], pa, x2, x3);
            }
        }
        rs0 += __shfl_xor_sync(0xffffffffu, rs0, 1);
        rs0 += __shfl_xor_sync(0xffffffffu, rs0, 2);
        rs1 += __shfl_xor_sync(0xffffffffu, rs1, 1);
        rs1 += __shfl_xor_sync(0xffffffffu, rs1, 2);
        lc0 = lc0 * sc0 + rs0;
        lc1 = lc1 * sc1 + rs1;
    }

    // ---- epilogue ----
    {
        int q = lane >> 2;
        int cb = (lane & 3) * 2;
        int r_lo = row0 + m0 + q;
        int r_hi = r_lo + 8;
        float* olo = g_Opart[half] + (size_t)r_lo * DIM;
        float* ohi = g_Opart[half] + (size_t)r_hi * DIM;
#pragma unroll
        for (int t = 0; t < 8; t++) {
            olo[t * 8 + cb]     = o[t][0];
            olo[t * 8 + cb + 1] = o[t][1];
            ohi[t * 8 + cb]     = o[t][2];
            ohi[t * 8 + cb + 1] = o[t][3];
        }
        if ((lane & 3) == 0) {
            g_mpart[half][r_lo] = mc0; g_mpart[half][r_hi] = mc1;
            g_lpart[half][r_lo] = lc0; g_lpart[half][r_hi] = lc1;
        }
    }
}

// ---------------- combine ----------------
__global__ __launch_bounds__(256) void combine_kernel(float* __restrict__ out) {
    int idx = blockIdx.x * 256 + threadIdx.x;
    int row = idx >> 6;
    int c = idx & 63;
    float m0 = g_mpart[0][row], m1 = g_mpart[1][row];
    float M = fmaxf(m0, m1);
    float w0 = __expf(m0 - M), w1 = __expf(m1 - M);
    float inv = 1.0f / (g_lpart[0][row] * w0 + g_lpart[1][row] * w1);
    out[(size_t)row * DIM + c] =
        (g_Opart[0][(size_t)row * DIM + c] * w0 + g_Opart[1][(size_t)row * DIM + c] * w1) * inv;
}

extern "C" void kernel_launch(void* const* d_in, const int* in_sizes, int n_in,
                              void* d_out, int out_size) {
    const float* x = (const float*)d_in[0];
    const float* R = (const float*)d_in[1];
    const float* E = (const float*)d_in[2];
    float* out = (float*)d_out;

    cudaFuncSetAttribute(proj_kernel, cudaFuncAttributeMaxDynamicSharedMemorySize, PROJ_SMEM);
    proj_kernel<<<N_TOK / 32, 256, PROJ_SMEM>>>(x, R, E);

    cudaFuncSetAttribute(attn_kernel, cudaFuncAttributeMaxDynamicSharedMemorySize, SMEM_TOTAL);
    attn_kernel<<<(N_TOK / BM) * 2, 128, SMEM_TOTAL>>>();

    combine_kernel<<<(N_TOK * DIM) / 256, 256>>>(out);
}